// round 5
// baseline (speedup 1.0000x reference)
#include <cuda_runtime.h>
#include <cuda_bf16.h>
#include <cuda_fp16.h>
#include <math.h>

// Problem constants (shapes are fixed for this problem instance)
#define NN      100000
#define NE      3200000
#define FIN     512
#define HID     64
#define NCLS    47
#define KHOPS   10
#define ALPHA   0.1f

// -------- device scratch (no allocations allowed) --------
__device__ int   g_count[NN];        // in-degree counts (real edges only)
__device__ int   g_colptr[NN + 1];   // CSR row pointers (by destination)
__device__ int   g_cursor[NN];       // scatter cursors
__device__ float g_dis[NN];          // D^-1/2 (deg incl. self loop)
__device__ int   g_incl[NN];         // inclusive per-block scan temp
__device__ int   g_blksum[256];      // block sums for scan
__device__ __align__(16) int g_edge[NE];  // src index, sorted by dst
__device__ __half g_Wt[(size_t)HID * FIN];               // W^T in fp16, [64][512]
__device__ __align__(256) float g_h0[(size_t)NN * HID];   // fp32 anchor
__device__ __align__(256) float g_hF[(size_t)NN * HID];   // final fp32 h
__device__ __align__(256) __half2 g_hsA[(size_t)NN * 32]; // scaled fp16 state
__device__ __align__(256) __half2 g_hsB[(size_t)NN * 32];

// ---------------- CSR build ----------------
__global__ void k_hist(const int* __restrict__ col, int e) {
    int i = blockIdx.x * blockDim.x + threadIdx.x;
    if (i < e) atomicAdd(&g_count[col[i]], 1);
}

// Hillis-Steele block scan (1024/block); also computes g_dis
__global__ void k_scan_block(int n) {
    __shared__ int s[1024];
    int i = blockIdx.x * 1024 + threadIdx.x;
    int v = (i < n) ? g_count[i] : 0;
    if (i < n) g_dis[i] = rsqrtf((float)(v + 1));  // +1 self loop
    s[threadIdx.x] = v;
    __syncthreads();
    #pragma unroll
    for (int off = 1; off < 1024; off <<= 1) {
        int t = (threadIdx.x >= off) ? s[threadIdx.x - off] : 0;
        __syncthreads();
        s[threadIdx.x] += t;
        __syncthreads();
    }
    if (i < n) g_incl[i] = s[threadIdx.x];
    if (threadIdx.x == 1023) g_blksum[blockIdx.x] = s[1023];
}

__global__ void k_scan_sums(int nb) {
    if (blockIdx.x == 0 && threadIdx.x == 0) {
        int acc = 0;
        for (int b = 0; b < nb; b++) { int t = g_blksum[b]; g_blksum[b] = acc; acc += t; }
    }
}

__global__ void k_finalize(int n) {
    int i = blockIdx.x * blockDim.x + threadIdx.x;
    if (i == 0) g_colptr[0] = 0;
    if (i < n) {
        int e = g_incl[i] + g_blksum[i >> 10];
        g_colptr[i + 1] = e;
        g_cursor[i] = e - g_count[i];
    }
}

__global__ void k_scatter_edges(const int* __restrict__ row, const int* __restrict__ col, int e) {
    int i = blockIdx.x * blockDim.x + threadIdx.x;
    if (i >= e) return;
    int c = col[i];
    int pos = atomicAdd(&g_cursor[c], 1);
    g_edge[pos] = row[i];
}

// ---------------- W preconvert: g_Wt[n][k] = (half)W[k][n] ----------------
__global__ void k_wconv(const float* __restrict__ W) {
    int i = blockIdx.x * blockDim.x + threadIdx.x;
    if (i < FIN * HID) {
        int k = i >> 6, nn = i & 63;
        g_Wt[(size_t)nn * FIN + k] = __float2half(W[(size_t)k * HID + nn]);
    }
}

// ---------------- Embed GEMM via tensor cores ----------------
// H0 = relu(X @ W + b), fp16 inputs / fp32 accumulate.
// Block: 256 threads (8 warps), tile 128 rows x 64 cols; warp = 16 rows x 64 cols.
#define KC 64
#define XP 8   // halves of padding per smem row
__global__ __launch_bounds__(256) void k_embed_mma(const float* __restrict__ X,
                                                   const float* __restrict__ b, int n) {
    __shared__ __align__(16) __half Xs[128][KC + XP];   // 18.4 KB
    __shared__ __align__(16) __half Ws[64][KC + XP];    // 9.2 KB
    __shared__ float bs[HID];
    int tid = threadIdx.x;
    int wid = tid >> 5, lane = tid & 31;
    int g  = lane >> 2;          // 0..7
    int cq = (lane & 3) * 2;     // 0,2,4,6
    int rowBase = blockIdx.x * 128;
    if (tid < HID) bs[tid] = b[tid];

    float acc[8][4];
    #pragma unroll
    for (int i = 0; i < 8; i++)
        #pragma unroll
        for (int j = 0; j < 4; j++) acc[i][j] = 0.f;

    for (int k0 = 0; k0 < FIN; k0 += KC) {
        {   // X chunk: 128 rows x 64 k; 2 threads/row, 32 floats each, convert to fp16
            int r  = tid >> 1;
            int ks = (tid & 1) * 32;
            int grow = rowBase + r;
            __half2* dst = (__half2*)&Xs[r][ks];
            if (grow < n) {
                const float* p = X + (size_t)grow * FIN + k0 + ks;
                #pragma unroll
                for (int i = 0; i < 8; i++) {
                    float4 v = *(const float4*)(p + i * 4);
                    dst[i * 2 + 0] = __floats2half2_rn(v.x, v.y);
                    dst[i * 2 + 1] = __floats2half2_rn(v.z, v.w);
                }
            } else {
                #pragma unroll
                for (int i = 0; i < 16; i++) dst[i] = __floats2half2_rn(0.f, 0.f);
            }
        }
        {   // W chunk: 64 n x 64 k from preconverted g_Wt
            int nn = tid >> 2;
            int ks = (tid & 3) * 16;
            const uint4* p = (const uint4*)(g_Wt + (size_t)nn * FIN + k0 + ks);
            uint4 v0 = p[0], v1 = p[1];
            *(uint4*)&Ws[nn][ks]     = v0;
            *(uint4*)&Ws[nn][ks + 8] = v1;
        }
        __syncthreads();
        #pragma unroll
        for (int kk = 0; kk < KC; kk += 16) {
            unsigned a0 = *(const unsigned*)&Xs[wid * 16 + g][kk + cq];
            unsigned a1 = *(const unsigned*)&Xs[wid * 16 + g + 8][kk + cq];
            unsigned a2 = *(const unsigned*)&Xs[wid * 16 + g][kk + cq + 8];
            unsigned a3 = *(const unsigned*)&Xs[wid * 16 + g + 8][kk + cq + 8];
            #pragma unroll
            for (int cb = 0; cb < 8; cb++) {
                unsigned b0 = *(const unsigned*)&Ws[cb * 8 + g][kk + cq];
                unsigned b1 = *(const unsigned*)&Ws[cb * 8 + g][kk + cq + 8];
                asm volatile(
                    "mma.sync.aligned.m16n8k16.row.col.f32.f16.f16.f32 "
                    "{%0,%1,%2,%3}, {%4,%5,%6,%7}, {%8,%9}, {%0,%1,%2,%3};"
                    : "+f"(acc[cb][0]), "+f"(acc[cb][1]),
                      "+f"(acc[cb][2]), "+f"(acc[cb][3])
                    : "r"(a0), "r"(a1), "r"(a2), "r"(a3), "r"(b0), "r"(b1));
            }
        }
        __syncthreads();
    }

    // epilogue: bias + relu -> g_h0 (fp32) and dis-scaled fp16 state -> g_hsA
    int r0 = rowBase + wid * 16 + g;
    int r1 = r0 + 8;
    float d0 = (r0 < n) ? g_dis[r0] : 0.f;
    float d1 = (r1 < n) ? g_dis[r1] : 0.f;
    #pragma unroll
    for (int cb = 0; cb < 8; cb++) {
        int c = cb * 8 + cq;
        float bx = bs[c], by = bs[c + 1];
        if (r0 < n) {
            float v0 = fmaxf(acc[cb][0] + bx, 0.f);
            float v1 = fmaxf(acc[cb][1] + by, 0.f);
            *(float2*)(g_h0 + (size_t)r0 * HID + c) = make_float2(v0, v1);
            g_hsA[(size_t)r0 * 32 + (c >> 1)] = __floats2half2_rn(d0 * v0, d0 * v1);
        }
        if (r1 < n) {
            float v0 = fmaxf(acc[cb][2] + bx, 0.f);
            float v1 = fmaxf(acc[cb][3] + by, 0.f);
            *(float2*)(g_h0 + (size_t)r1 * HID + c) = make_float2(v0, v1);
            g_hsA[(size_t)r1 * 32 + (c >> 1)] = __floats2half2_rn(d1 * v0, d1 * v1);
        }
    }
}

// ---------------- Propagation hop ----------------
// hs = dis (.) h (fp16).  out[v] = 0.9*dis[v]*(sum_{edges} hs[src] + hs[v]) + 0.1*h0[v]
__global__ __launch_bounds__(256) void k_hop(const __half2* __restrict__ hs,
                                             __half2* __restrict__ hn,
                                             int n, int final_hop) {
    int warp = (blockIdx.x * blockDim.x + threadIdx.x) >> 5;
    int lane = threadIdx.x & 31;
    if (warp >= n) return;
    int beg = g_colptr[warp], end = g_colptr[warp + 1];

    float2 self = __half22float2(hs[(size_t)warp * 32 + lane]);
    float ax0 = self.x, ay0 = self.y;
    float ax1 = 0.f, ay1 = 0.f;

    int e = beg;
    // scalar head until 16B-aligned index
    while (e < end && (e & 3)) {
        float2 f = __half22float2(hs[(size_t)__ldg(&g_edge[e]) * 32 + lane]);
        ax0 += f.x; ay0 += f.y;
        e++;
    }
    // 8-edge main loop: two int4 index loads -> 8 independent gathers
    for (; e + 8 <= end; e += 8) {
        int4 q0 = *(const int4*)&g_edge[e];
        int4 q1 = *(const int4*)&g_edge[e + 4];
        float2 f0 = __half22float2(hs[(size_t)q0.x * 32 + lane]);
        float2 f1 = __half22float2(hs[(size_t)q0.y * 32 + lane]);
        float2 f2 = __half22float2(hs[(size_t)q0.z * 32 + lane]);
        float2 f3 = __half22float2(hs[(size_t)q0.w * 32 + lane]);
        float2 f4 = __half22float2(hs[(size_t)q1.x * 32 + lane]);
        float2 f5 = __half22float2(hs[(size_t)q1.y * 32 + lane]);
        float2 f6 = __half22float2(hs[(size_t)q1.z * 32 + lane]);
        float2 f7 = __half22float2(hs[(size_t)q1.w * 32 + lane]);
        ax0 += f0.x; ay0 += f0.y;  ax1 += f1.x; ay1 += f1.y;
        ax0 += f2.x; ay0 += f2.y;  ax1 += f3.x; ay1 += f3.y;
        ax0 += f4.x; ay0 += f4.y;  ax1 += f5.x; ay1 += f5.y;
        ax0 += f6.x; ay0 += f6.y;  ax1 += f7.x; ay1 += f7.y;
    }
    // 4-edge loop
    for (; e + 4 <= end; e += 4) {
        int4 q0 = *(const int4*)&g_edge[e];
        float2 f0 = __half22float2(hs[(size_t)q0.x * 32 + lane]);
        float2 f1 = __half22float2(hs[(size_t)q0.y * 32 + lane]);
        float2 f2 = __half22float2(hs[(size_t)q0.z * 32 + lane]);
        float2 f3 = __half22float2(hs[(size_t)q0.w * 32 + lane]);
        ax0 += f0.x; ay0 += f0.y;  ax1 += f1.x; ay1 += f1.y;
        ax0 += f2.x; ay0 += f2.y;  ax1 += f3.x; ay1 += f3.y;
    }
    // scalar tail
    for (; e < end; e++) {
        float2 f = __half22float2(hs[(size_t)__ldg(&g_edge[e]) * 32 + lane]);
        ax0 += f.x; ay0 += f.y;
    }
    float ax = ax0 + ax1, ay = ay0 + ay1;

    float d = g_dis[warp];
    float2 h0v = *(const float2*)(g_h0 + (size_t)warp * HID + lane * 2);
    float ox = 0.9f * d * ax + 0.1f * h0v.x;
    float oy = 0.9f * d * ay + 0.1f * h0v.y;

    if (final_hop) {
        *(float2*)(g_hF + (size_t)warp * HID + lane * 2) = make_float2(ox, oy);
    } else {
        hn[(size_t)warp * 32 + lane] = __floats2half2_rn(d * ox, d * oy);
    }
}

// ---------------- Predict + softmax family ----------------
__global__ __launch_bounds__(256) void k_pred(const float* __restrict__ h,
                                              const float* __restrict__ Wp,
                                              const float* __restrict__ bp,
                                              float* __restrict__ out,
                                              int n, int out_size) {
    __shared__ float Ws[HID * NCLS];
    __shared__ float bs[NCLS];
    __shared__ float hsm[8][HID];
    for (int i = threadIdx.x; i < HID * NCLS; i += blockDim.x) Ws[i] = Wp[i];
    if (threadIdx.x < NCLS) bs[threadIdx.x] = bp[threadIdx.x];
    __syncthreads();

    int warp = threadIdx.x >> 5;
    int lane = threadIdx.x & 31;
    int v = blockIdx.x * 8 + warp;
    if (v >= n) return;

    hsm[warp][lane]      = h[(size_t)v * HID + lane];
    hsm[warp][lane + 32] = h[(size_t)v * HID + lane + 32];
    __syncwarp();

    int c1 = (lane + 32 < NCLS) ? (lane + 32) : (NCLS - 1);
    float a0 = bs[lane];
    float a1 = bs[c1];
    #pragma unroll
    for (int k = 0; k < HID; k++) {
        float hk = hsm[warp][k];
        a0 += hk * Ws[k * NCLS + lane];
        a1 += hk * Ws[k * NCLS + c1];
    }
    bool l1 = (lane + 32 < NCLS);

    float m = fmaxf(a0, l1 ? a1 : -INFINITY);
    #pragma unroll
    for (int o = 16; o > 0; o >>= 1) m = fmaxf(m, __shfl_xor_sync(0xffffffff, m, o));
    float e0 = __expf(a0 - m);
    float e1 = l1 ? __expf(a1 - m) : 0.f;
    float s = e0 + e1;
    #pragma unroll
    for (int o = 16; o > 0; o >>= 1) s += __shfl_xor_sync(0xffffffff, s, o);
    float lse = m + logf(s);
    float inv = 1.f / s;

    size_t base = (size_t)v * NCLS;
    size_t sec  = (size_t)n * NCLS;
    out[base + lane] = a0 - lse;
    if (l1) out[base + lane + 32] = a1 - lse;
    if (out_size >= 2 * (int)sec) {
        out[sec + base + lane] = a0;
        if (l1) out[sec + base + lane + 32] = a1;
    }
    if (out_size >= 3 * (int)sec) {
        out[2 * sec + base + lane] = e0 * inv;
        if (l1) out[2 * sec + base + lane + 32] = e1 * inv;
    }
}

// ---------------- launch ----------------
extern "C" void kernel_launch(void* const* d_in, const int* in_sizes, int n_in,
                              void* d_out, int out_size) {
    const float* x     = (const float*)d_in[0];   // [N,512]
    const int*   eidx  = (const int*)d_in[1];     // [2,E]
    const float* Wemb  = (const float*)d_in[2];   // [512,64]
    const float* bemb  = (const float*)d_in[3];   // [64]
    const float* Wpred = (const float*)d_in[4];   // [64,47]
    const float* bpred = (const float*)d_in[5];   // [47]
    float* out = (float*)d_out;

    int n = in_sizes[0] / FIN;
    int e = in_sizes[1] / 2;
    const int* row = eidx;       // source
    const int* col = eidx + e;   // target

    int nbE  = (e + 255) / 256;
    int nbS  = (n + 1023) / 1024;

    // --- degree + GCN norm + CSR by destination (real edges only) ---
    {
        void* cntp; cudaGetSymbolAddress(&cntp, g_count);
        cudaMemsetAsync(cntp, 0, (size_t)n * sizeof(int));
    }
    k_hist<<<nbE, 256>>>(col, e);
    k_scan_block<<<nbS, 1024>>>(n);   // also computes g_dis
    k_scan_sums<<<1, 32>>>(nbS);
    k_finalize<<<nbS, 1024>>>(n);
    k_scatter_edges<<<nbE, 256>>>(row, col, e);

    // --- embed: preconvert W to fp16, then tensor-core GEMM ---
    k_wconv<<<(FIN * HID + 255) / 256, 256>>>(Wemb);
    k_embed_mma<<<(n + 127) / 128, 256>>>(x, bemb, n);

    // --- 10 propagation hops (ping-pong fp16 scaled state) ---
    int hopBlocks = (n * 32 + 255) / 256;
    {
        __half2* hAp; cudaGetSymbolAddress((void**)&hAp, g_hsA);
        __half2* hBp; cudaGetSymbolAddress((void**)&hBp, g_hsB);
        __half2* cur = hAp;
        for (int i = 0; i < KHOPS; i++) {
            int fin = (i == KHOPS - 1);
            __half2* dst = (cur == hAp) ? hBp : hAp;
            k_hop<<<hopBlocks, 256>>>(cur, dst, n, fin);
            cur = dst;
        }
    }

    // --- predict + softmax family (reads fp32 g_hF) ---
    float* hFp; cudaGetSymbolAddress((void**)&hFp, g_hF);
    k_pred<<<(n + 7) / 8, 256>>>(hFp, Wpred, bpred, out, n, out_size);
}

// round 6
// speedup vs baseline: 1.0620x; 1.0620x over previous
#include <cuda_runtime.h>
#include <cuda_bf16.h>
#include <cuda_fp16.h>
#include <math.h>

// Problem constants (shapes are fixed for this problem instance)
#define NN      100000
#define NE      3200000
#define FIN     512
#define HID     64
#define NCLS    47
#define KHOPS   10
#define ALPHA   0.1f

// -------- device scratch (no allocations allowed) --------
__device__ int   g_count[NN];        // in-degree counts (real edges only)
__device__ int   g_colptr[NN + 1];   // CSR row pointers (by destination)
__device__ int   g_cursor[NN];       // scatter cursors
__device__ float g_dis[NN];          // D^-1/2 (deg incl. self loop)
__device__ int   g_incl[NN];         // inclusive per-block scan temp
__device__ int   g_blksum[256];      // block sums for scan
__device__ __align__(16) int g_edge[NE];  // src index, sorted by dst
__device__ __half g_Wt[(size_t)HID * FIN];               // W^T in fp16, [64][512]
__device__ __align__(256) float g_h0[(size_t)NN * HID];   // fp32 anchor
__device__ __align__(256) float g_hF[(size_t)NN * HID];   // final fp32 h
__device__ __align__(256) __half2 g_hsA[(size_t)NN * 32]; // scaled fp16 state
__device__ __align__(256) __half2 g_hsB[(size_t)NN * 32];

// ---------------- CSR build ----------------
__global__ void k_hist(const int* __restrict__ col, int e) {
    int i4 = (blockIdx.x * blockDim.x + threadIdx.x) * 4;
    if (i4 + 4 <= e) {
        int4 c = *(const int4*)(col + i4);
        atomicAdd(&g_count[c.x], 1);
        atomicAdd(&g_count[c.y], 1);
        atomicAdd(&g_count[c.z], 1);
        atomicAdd(&g_count[c.w], 1);
    } else {
        for (int i = i4; i < e; i++) atomicAdd(&g_count[col[i]], 1);
    }
}

// Hillis-Steele block scan (1024/block); also computes g_dis
__global__ void k_scan_block(int n) {
    __shared__ int s[1024];
    int i = blockIdx.x * 1024 + threadIdx.x;
    int v = (i < n) ? g_count[i] : 0;
    if (i < n) g_dis[i] = rsqrtf((float)(v + 1));  // +1 self loop
    s[threadIdx.x] = v;
    __syncthreads();
    #pragma unroll
    for (int off = 1; off < 1024; off <<= 1) {
        int t = (threadIdx.x >= off) ? s[threadIdx.x - off] : 0;
        __syncthreads();
        s[threadIdx.x] += t;
        __syncthreads();
    }
    if (i < n) g_incl[i] = s[threadIdx.x];
    if (threadIdx.x == 1023) g_blksum[blockIdx.x] = s[1023];
}

__global__ void k_scan_sums(int nb) {
    if (blockIdx.x == 0 && threadIdx.x == 0) {
        int acc = 0;
        for (int b = 0; b < nb; b++) { int t = g_blksum[b]; g_blksum[b] = acc; acc += t; }
    }
}

__global__ void k_finalize(int n) {
    int i = blockIdx.x * blockDim.x + threadIdx.x;
    if (i == 0) g_colptr[0] = 0;
    if (i < n) {
        int e = g_incl[i] + g_blksum[i >> 10];
        g_colptr[i + 1] = e;
        g_cursor[i] = e - g_count[i];
    }
}

__global__ void k_scatter_edges(const int* __restrict__ row, const int* __restrict__ col, int e) {
    int i = blockIdx.x * blockDim.x + threadIdx.x;
    if (i >= e) return;
    int c = col[i];
    int pos = atomicAdd(&g_cursor[c], 1);
    g_edge[pos] = row[i];
}

// ---------------- W preconvert: g_Wt[n][k] = (half)W[k][n] ----------------
__global__ void k_wconv(const float* __restrict__ W) {
    int i = blockIdx.x * blockDim.x + threadIdx.x;
    if (i < FIN * HID) {
        int k = i >> 6, nn = i & 63;
        g_Wt[(size_t)nn * FIN + k] = __float2half(W[(size_t)k * HID + nn]);
    }
}

// ---------------- Embed GEMM via tensor cores ----------------
// H0 = relu(X @ W + b), fp16 inputs / fp32 accumulate.
// Block: 256 threads (8 warps), tile 128 rows x 64 cols; warp = 16 rows x 64 cols.
#define KC 64
#define XP 8   // halves of padding per smem row
__global__ __launch_bounds__(256) void k_embed_mma(const float* __restrict__ X,
                                                   const float* __restrict__ b, int n) {
    __shared__ __align__(16) __half Xs[128][KC + XP];   // 18.4 KB
    __shared__ __align__(16) __half Ws[64][KC + XP];    // 9.2 KB
    __shared__ float bs[HID];
    int tid = threadIdx.x;
    int wid = tid >> 5, lane = tid & 31;
    int g  = lane >> 2;          // 0..7
    int cq = (lane & 3) * 2;     // 0,2,4,6
    int rowBase = blockIdx.x * 128;
    if (tid < HID) bs[tid] = b[tid];

    float acc[8][4];
    #pragma unroll
    for (int i = 0; i < 8; i++)
        #pragma unroll
        for (int j = 0; j < 4; j++) acc[i][j] = 0.f;

    for (int k0 = 0; k0 < FIN; k0 += KC) {
        {   // X chunk: 128 rows x 64 k; 2 threads/row, 32 floats each, convert to fp16
            int r  = tid >> 1;
            int ks = (tid & 1) * 32;
            int grow = rowBase + r;
            __half2* dst = (__half2*)&Xs[r][ks];
            if (grow < n) {
                const float* p = X + (size_t)grow * FIN + k0 + ks;
                #pragma unroll
                for (int i = 0; i < 8; i++) {
                    float4 v = *(const float4*)(p + i * 4);
                    dst[i * 2 + 0] = __floats2half2_rn(v.x, v.y);
                    dst[i * 2 + 1] = __floats2half2_rn(v.z, v.w);
                }
            } else {
                #pragma unroll
                for (int i = 0; i < 16; i++) dst[i] = __floats2half2_rn(0.f, 0.f);
            }
        }
        {   // W chunk: 64 n x 64 k from preconverted g_Wt
            int nn = tid >> 2;
            int ks = (tid & 3) * 16;
            const uint4* p = (const uint4*)(g_Wt + (size_t)nn * FIN + k0 + ks);
            uint4 v0 = p[0], v1 = p[1];
            *(uint4*)&Ws[nn][ks]     = v0;
            *(uint4*)&Ws[nn][ks + 8] = v1;
        }
        __syncthreads();
        #pragma unroll
        for (int kk = 0; kk < KC; kk += 16) {
            unsigned a0 = *(const unsigned*)&Xs[wid * 16 + g][kk + cq];
            unsigned a1 = *(const unsigned*)&Xs[wid * 16 + g + 8][kk + cq];
            unsigned a2 = *(const unsigned*)&Xs[wid * 16 + g][kk + cq + 8];
            unsigned a3 = *(const unsigned*)&Xs[wid * 16 + g + 8][kk + cq + 8];
            #pragma unroll
            for (int cb = 0; cb < 8; cb++) {
                unsigned b0 = *(const unsigned*)&Ws[cb * 8 + g][kk + cq];
                unsigned b1 = *(const unsigned*)&Ws[cb * 8 + g][kk + cq + 8];
                asm volatile(
                    "mma.sync.aligned.m16n8k16.row.col.f32.f16.f16.f32 "
                    "{%0,%1,%2,%3}, {%4,%5,%6,%7}, {%8,%9}, {%0,%1,%2,%3};"
                    : "+f"(acc[cb][0]), "+f"(acc[cb][1]),
                      "+f"(acc[cb][2]), "+f"(acc[cb][3])
                    : "r"(a0), "r"(a1), "r"(a2), "r"(a3), "r"(b0), "r"(b1));
            }
        }
        __syncthreads();
    }

    // epilogue: bias + relu -> g_h0 (fp32) and dis-scaled fp16 state -> g_hsA
    int r0 = rowBase + wid * 16 + g;
    int r1 = r0 + 8;
    float d0 = (r0 < n) ? g_dis[r0] : 0.f;
    float d1 = (r1 < n) ? g_dis[r1] : 0.f;
    #pragma unroll
    for (int cb = 0; cb < 8; cb++) {
        int c = cb * 8 + cq;
        float bx = bs[c], by = bs[c + 1];
        if (r0 < n) {
            float v0 = fmaxf(acc[cb][0] + bx, 0.f);
            float v1 = fmaxf(acc[cb][1] + by, 0.f);
            *(float2*)(g_h0 + (size_t)r0 * HID + c) = make_float2(v0, v1);
            g_hsA[(size_t)r0 * 32 + (c >> 1)] = __floats2half2_rn(d0 * v0, d0 * v1);
        }
        if (r1 < n) {
            float v0 = fmaxf(acc[cb][2] + bx, 0.f);
            float v1 = fmaxf(acc[cb][3] + by, 0.f);
            *(float2*)(g_h0 + (size_t)r1 * HID + c) = make_float2(v0, v1);
            g_hsA[(size_t)r1 * 32 + (c >> 1)] = __floats2half2_rn(d1 * v0, d1 * v1);
        }
    }
}

// ---------------- Propagation hop (R3 form: 4-deep scalar, known-good) ----------------
// hs = dis (.) h (fp16).  out[v] = 0.9*dis[v]*(sum_{edges} hs[src] + hs[v]) + 0.1*h0[v]
__global__ __launch_bounds__(256) void k_hop(const __half2* __restrict__ hs,
                                             __half2* __restrict__ hn,
                                             int n, int final_hop) {
    int warp = (blockIdx.x * blockDim.x + threadIdx.x) >> 5;
    int lane = threadIdx.x & 31;
    if (warp >= n) return;
    int beg = g_colptr[warp], end = g_colptr[warp + 1];

    float2 self = __half22float2(hs[(size_t)warp * 32 + lane]);
    float ax0 = self.x, ay0 = self.y;
    float ax1 = 0.f, ay1 = 0.f;

    int e = beg;
    for (; e + 3 < end; e += 4) {
        int s0 = __ldg(&g_edge[e]);
        int s1 = __ldg(&g_edge[e + 1]);
        int s2 = __ldg(&g_edge[e + 2]);
        int s3 = __ldg(&g_edge[e + 3]);
        float2 f0 = __half22float2(hs[(size_t)s0 * 32 + lane]);
        float2 f1 = __half22float2(hs[(size_t)s1 * 32 + lane]);
        float2 f2 = __half22float2(hs[(size_t)s2 * 32 + lane]);
        float2 f3 = __half22float2(hs[(size_t)s3 * 32 + lane]);
        ax0 += f0.x; ay0 += f0.y;
        ax1 += f1.x; ay1 += f1.y;
        ax0 += f2.x; ay0 += f2.y;
        ax1 += f3.x; ay1 += f3.y;
    }
    for (; e < end; e++) {
        int s0 = __ldg(&g_edge[e]);
        float2 f0 = __half22float2(hs[(size_t)s0 * 32 + lane]);
        ax0 += f0.x; ay0 += f0.y;
    }
    float ax = ax0 + ax1, ay = ay0 + ay1;

    float d = g_dis[warp];
    float2 h0v = *(const float2*)(g_h0 + (size_t)warp * HID + lane * 2);
    float ox = 0.9f * d * ax + 0.1f * h0v.x;
    float oy = 0.9f * d * ay + 0.1f * h0v.y;

    if (final_hop) {
        *(float2*)(g_hF + (size_t)warp * HID + lane * 2) = make_float2(ox, oy);
    } else {
        hn[(size_t)warp * 32 + lane] = __floats2half2_rn(d * ox, d * oy);
    }
}

// ---------------- Predict + softmax family ----------------
__global__ __launch_bounds__(256) void k_pred(const float* __restrict__ h,
                                              const float* __restrict__ Wp,
                                              const float* __restrict__ bp,
                                              float* __restrict__ out,
                                              int n, int out_size) {
    __shared__ float Ws[HID * NCLS];
    __shared__ float bs[NCLS];
    __shared__ float hsm[8][HID];
    for (int i = threadIdx.x; i < HID * NCLS; i += blockDim.x) Ws[i] = Wp[i];
    if (threadIdx.x < NCLS) bs[threadIdx.x] = bp[threadIdx.x];
    __syncthreads();

    int warp = threadIdx.x >> 5;
    int lane = threadIdx.x & 31;
    int v = blockIdx.x * 8 + warp;
    if (v >= n) return;

    hsm[warp][lane]      = h[(size_t)v * HID + lane];
    hsm[warp][lane + 32] = h[(size_t)v * HID + lane + 32];
    __syncwarp();

    int c1 = (lane + 32 < NCLS) ? (lane + 32) : (NCLS - 1);
    float a0 = bs[lane];
    float a1 = bs[c1];
    #pragma unroll
    for (int k = 0; k < HID; k++) {
        float hk = hsm[warp][k];
        a0 += hk * Ws[k * NCLS + lane];
        a1 += hk * Ws[k * NCLS + c1];
    }
    bool l1 = (lane + 32 < NCLS);

    float m = fmaxf(a0, l1 ? a1 : -INFINITY);
    #pragma unroll
    for (int o = 16; o > 0; o >>= 1) m = fmaxf(m, __shfl_xor_sync(0xffffffff, m, o));
    float e0 = __expf(a0 - m);
    float e1 = l1 ? __expf(a1 - m) : 0.f;
    float s = e0 + e1;
    #pragma unroll
    for (int o = 16; o > 0; o >>= 1) s += __shfl_xor_sync(0xffffffff, s, o);
    float lse = m + logf(s);
    float inv = 1.f / s;

    size_t base = (size_t)v * NCLS;
    size_t sec  = (size_t)n * NCLS;
    out[base + lane] = a0 - lse;
    if (l1) out[base + lane + 32] = a1 - lse;
    if (out_size >= 2 * (int)sec) {
        out[sec + base + lane] = a0;
        if (l1) out[sec + base + lane + 32] = a1;
    }
    if (out_size >= 3 * (int)sec) {
        out[2 * sec + base + lane] = e0 * inv;
        if (l1) out[2 * sec + base + lane + 32] = e1 * inv;
    }
}

// ---------------- launch ----------------
extern "C" void kernel_launch(void* const* d_in, const int* in_sizes, int n_in,
                              void* d_out, int out_size) {
    const float* x     = (const float*)d_in[0];   // [N,512]
    const int*   eidx  = (const int*)d_in[1];     // [2,E]
    const float* Wemb  = (const float*)d_in[2];   // [512,64]
    const float* bemb  = (const float*)d_in[3];   // [64]
    const float* Wpred = (const float*)d_in[4];   // [64,47]
    const float* bpred = (const float*)d_in[5];   // [47]
    float* out = (float*)d_out;

    int n = in_sizes[0] / FIN;
    int e = in_sizes[1] / 2;
    const int* row = eidx;       // source
    const int* col = eidx + e;   // target

    int nbE  = (e + 255) / 256;
    int nbE4 = (e / 4 + 255) / 256 + 1;
    int nbS  = (n + 1023) / 1024;

    // Side stream + events for fork/join (created per call; kernel_launch is
    // invoked only a handful of times — replays re-execute the captured graph).
    cudaStream_t s2;
    cudaStreamCreate(&s2);
    cudaEvent_t evFork, evDis, evEmb;
    cudaEventCreateWithFlags(&evFork, cudaEventDisableTiming);
    cudaEventCreateWithFlags(&evDis,  cudaEventDisableTiming);
    cudaEventCreateWithFlags(&evEmb,  cudaEventDisableTiming);
    cudaStream_t s0 = (cudaStream_t)0;   // same default stream the <<<>>> launches use

    // fork: side stream starts with W preconvert (depends only on input)
    cudaEventRecord(evFork, s0);
    cudaStreamWaitEvent(s2, evFork, 0);
    k_wconv<<<(FIN * HID + 255) / 256, 256, 0, s2>>>(Wemb);

    // main: degree histogram + scan (produces g_dis)
    {
        void* cntp; cudaGetSymbolAddress(&cntp, g_count);
        cudaMemsetAsync(cntp, 0, (size_t)n * sizeof(int), s0);
    }
    k_hist<<<nbE4, 256>>>(col, e);
    k_scan_block<<<nbS, 1024>>>(n);   // also computes g_dis
    cudaEventRecord(evDis, s0);

    // side: embed GEMM (needs g_dis for epilogue scaling)
    cudaStreamWaitEvent(s2, evDis, 0);
    k_embed_mma<<<(n + 127) / 128, 256, 0, s2>>>(x, bemb, n);
    cudaEventRecord(evEmb, s2);

    // main (overlapping with embed): finish CSR build
    k_scan_sums<<<1, 32>>>(nbS);
    k_finalize<<<nbS, 1024>>>(n);
    k_scatter_edges<<<nbE, 256>>>(row, col, e);

    // join: hops need both CSR (main) and h0/hsA (side)
    cudaStreamWaitEvent(s0, evEmb, 0);

    // --- 10 propagation hops (ping-pong fp16 scaled state) ---
    int hopBlocks = (n * 32 + 255) / 256;
    {
        __half2* hAp; cudaGetSymbolAddress((void**)&hAp, g_hsA);
        __half2* hBp; cudaGetSymbolAddress((void**)&hBp, g_hsB);
        __half2* cur = hAp;
        for (int i = 0; i < KHOPS; i++) {
            int fin = (i == KHOPS - 1);
            __half2* dst = (cur == hAp) ? hBp : hAp;
            k_hop<<<hopBlocks, 256>>>(cur, dst, n, fin);
            cur = dst;
        }
    }

    // --- predict + softmax family (reads fp32 g_hF) ---
    float* hFp; cudaGetSymbolAddress((void**)&hFp, g_hF);
    k_pred<<<(n + 7) / 8, 256>>>(hFp, Wpred, bpred, out, n, out_size);
}

// round 7
// speedup vs baseline: 1.0707x; 1.0082x over previous
#include <cuda_runtime.h>
#include <cuda_bf16.h>
#include <cuda_fp16.h>
#include <math.h>

// Problem constants (shapes are fixed for this problem instance)
#define NN      100000
#define NE      3200000
#define FIN     512
#define HID     64
#define NCLS    47
#define KHOPS   10
#define ALPHA   0.1f

// -------- device scratch (no allocations allowed) --------
__device__ int   g_count[NN];        // in-degree counts (real edges only)
__device__ int   g_colptr[NN + 1];   // CSR row pointers (by destination)
__device__ int   g_cursor[NN];       // scatter cursors
__device__ float g_dis[NN];          // D^-1/2 (deg incl. self loop)
__device__ int   g_incl[NN];         // inclusive per-block scan temp
__device__ int   g_blksum[256];      // block sums for scan
__device__ __align__(16) int g_edge[NE];  // src index, sorted by dst
__device__ __half g_Wt[(size_t)HID * FIN];                     // W^T fp16 [64][512]
__device__ __align__(16) __half g_X16[(size_t)(NN + 128) * FIN]; // X in fp16 (+pad rows)
__device__ __align__(256) float g_h0[(size_t)NN * HID];   // fp32 anchor
__device__ __align__(256) float g_hF[(size_t)NN * HID];   // final fp32 h
__device__ __align__(256) __half2 g_hsA[(size_t)NN * 32]; // scaled fp16 state
__device__ __align__(256) __half2 g_hsB[(size_t)NN * 32];

// ---------------- cp.async helpers ----------------
__device__ __forceinline__ void cp16(void* smem, const void* gmem) {
    unsigned s = (unsigned)__cvta_generic_to_shared(smem);
    asm volatile("cp.async.ca.shared.global [%0], [%1], 16;\n" :: "r"(s), "l"(gmem));
}
__device__ __forceinline__ void cp_commit() {
    asm volatile("cp.async.commit_group;\n");
}
template <int N>
__device__ __forceinline__ void cp_wait() {
    asm volatile("cp.async.wait_group %0;\n" :: "n"(N));
}

// ---------------- CSR build ----------------
__global__ void k_hist(const int* __restrict__ col, int e) {
    int i4 = (blockIdx.x * blockDim.x + threadIdx.x) * 4;
    if (i4 + 4 <= e) {
        int4 c = *(const int4*)(col + i4);
        atomicAdd(&g_count[c.x], 1);
        atomicAdd(&g_count[c.y], 1);
        atomicAdd(&g_count[c.z], 1);
        atomicAdd(&g_count[c.w], 1);
    } else {
        for (int i = i4; i < e; i++) atomicAdd(&g_count[col[i]], 1);
    }
}

// Hillis-Steele block scan (1024/block); also computes g_dis
__global__ void k_scan_block(int n) {
    __shared__ int s[1024];
    int i = blockIdx.x * 1024 + threadIdx.x;
    int v = (i < n) ? g_count[i] : 0;
    if (i < n) g_dis[i] = rsqrtf((float)(v + 1));  // +1 self loop
    s[threadIdx.x] = v;
    __syncthreads();
    #pragma unroll
    for (int off = 1; off < 1024; off <<= 1) {
        int t = (threadIdx.x >= off) ? s[threadIdx.x - off] : 0;
        __syncthreads();
        s[threadIdx.x] += t;
        __syncthreads();
    }
    if (i < n) g_incl[i] = s[threadIdx.x];
    if (threadIdx.x == 1023) g_blksum[blockIdx.x] = s[1023];
}

__global__ void k_scan_sums(int nb) {
    if (blockIdx.x == 0 && threadIdx.x == 0) {
        int acc = 0;
        for (int b = 0; b < nb; b++) { int t = g_blksum[b]; g_blksum[b] = acc; acc += t; }
    }
}

__global__ void k_finalize(int n) {
    int i = blockIdx.x * blockDim.x + threadIdx.x;
    if (i == 0) g_colptr[0] = 0;
    if (i < n) {
        int e = g_incl[i] + g_blksum[i >> 10];
        g_colptr[i + 1] = e;
        g_cursor[i] = e - g_count[i];
    }
}

__global__ void k_scatter_edges(const int* __restrict__ row, const int* __restrict__ col, int e) {
    int i = blockIdx.x * blockDim.x + threadIdx.x;
    if (i >= e) return;
    int c = col[i];
    int pos = atomicAdd(&g_cursor[c], 1);
    g_edge[pos] = row[i];
}

// ---------------- W preconvert: g_Wt[n][k] = (half)W[k][n] ----------------
__global__ void k_wconv(const float* __restrict__ W) {
    int i = blockIdx.x * blockDim.x + threadIdx.x;
    if (i < FIN * HID) {
        int k = i >> 6, nn = i & 63;
        g_Wt[(size_t)nn * FIN + k] = __float2half(W[(size_t)k * HID + nn]);
    }
}

// ---------------- X preconvert: fp32 -> fp16 (same rounding as before) ----------------
__global__ __launch_bounds__(256) void k_xconv(const float* __restrict__ X, int total) {
    int i = (blockIdx.x * blockDim.x + threadIdx.x) * 8;
    if (i + 8 <= total) {
        float4 a = *(const float4*)(X + i);
        float4 b = *(const float4*)(X + i + 4);
        __half2 h0 = __floats2half2_rn(a.x, a.y);
        __half2 h1 = __floats2half2_rn(a.z, a.w);
        __half2 h2 = __floats2half2_rn(b.x, b.y);
        __half2 h3 = __floats2half2_rn(b.z, b.w);
        uint4 v;
        v.x = *(unsigned*)&h0; v.y = *(unsigned*)&h1;
        v.z = *(unsigned*)&h2; v.w = *(unsigned*)&h3;
        *(uint4*)(g_X16 + i) = v;
    } else {
        for (int j = i; j < total; j++) g_X16[j] = __float2half(X[j]);
    }
}

// ---------------- Embed GEMM via tensor cores, cp.async double-buffered ----------------
// H0 = relu(X @ W + b), fp16 inputs / fp32 accumulate.
// Block: 256 threads (8 warps), tile 128 rows x 64 cols; warp = 16 rows x 64 cols.
#define KC 32
#define XSTR (KC + 8)      // padded smem row stride in halves (80 B: conflict-free frags)
#define NCHUNK (FIN / KC)  // 16
__global__ __launch_bounds__(256) void k_embed_mma(const float* __restrict__ b, int n) {
    __shared__ __align__(16) __half Xs[2][128][XSTR];   // 20.0 KB
    __shared__ __align__(16) __half Ws[2][64][XSTR];    // 10.0 KB
    __shared__ float bs[HID];
    int tid = threadIdx.x;
    int wid = tid >> 5, lane = tid & 31;
    int g  = lane >> 2;          // 0..7
    int cq = (lane & 3) * 2;     // 0,2,4,6
    int rowBase = blockIdx.x * 128;
    if (tid < HID) bs[tid] = b[tid];

    // per-thread load assignments
    int xr = tid >> 1;            // 0..127 (X row)
    int xp = (tid & 1) * 16;      // 0 or 16 halves
    const __half* xsrc = g_X16 + (size_t)(rowBase + xr) * FIN + xp;  // padded rows: safe OOB
    int wr = tid >> 2;            // 0..63 (W row)
    int wq = (tid & 3) * 8;       // 0,8,16,24 halves
    const __half* wsrc = g_Wt + (size_t)wr * FIN + wq;

    float acc[8][4];
    #pragma unroll
    for (int i = 0; i < 8; i++)
        #pragma unroll
        for (int j = 0; j < 4; j++) acc[i][j] = 0.f;

    // prologue: issue chunk 0 into stage 0
    cp16(&Xs[0][xr][xp],     xsrc);
    cp16(&Xs[0][xr][xp + 8], xsrc + 8);
    cp16(&Ws[0][wr][wq],     wsrc);
    cp_commit();

    for (int c = 0; c < NCHUNK; c++) {
        int st = c & 1;
        if (c + 1 < NCHUNK) {
            int ns = (c + 1) & 1;
            int k0 = (c + 1) * KC;
            cp16(&Xs[ns][xr][xp],     xsrc + k0);
            cp16(&Xs[ns][xr][xp + 8], xsrc + k0 + 8);
            cp16(&Ws[ns][wr][wq],     wsrc + k0);
            cp_commit();
            cp_wait<1>();
        } else {
            cp_wait<0>();
        }
        __syncthreads();

        #pragma unroll
        for (int kk = 0; kk < KC; kk += 16) {
            unsigned a0 = *(const unsigned*)&Xs[st][wid * 16 + g][kk + cq];
            unsigned a1 = *(const unsigned*)&Xs[st][wid * 16 + g + 8][kk + cq];
            unsigned a2 = *(const unsigned*)&Xs[st][wid * 16 + g][kk + cq + 8];
            unsigned a3 = *(const unsigned*)&Xs[st][wid * 16 + g + 8][kk + cq + 8];
            #pragma unroll
            for (int cb = 0; cb < 8; cb++) {
                unsigned b0 = *(const unsigned*)&Ws[st][cb * 8 + g][kk + cq];
                unsigned b1 = *(const unsigned*)&Ws[st][cb * 8 + g][kk + cq + 8];
                asm volatile(
                    "mma.sync.aligned.m16n8k16.row.col.f32.f16.f16.f32 "
                    "{%0,%1,%2,%3}, {%4,%5,%6,%7}, {%8,%9}, {%0,%1,%2,%3};"
                    : "+f"(acc[cb][0]), "+f"(acc[cb][1]),
                      "+f"(acc[cb][2]), "+f"(acc[cb][3])
                    : "r"(a0), "r"(a1), "r"(a2), "r"(a3), "r"(b0), "r"(b1));
            }
        }
        __syncthreads();
    }

    // epilogue: bias + relu -> g_h0 (fp32) and dis-scaled fp16 state -> g_hsA
    int r0 = rowBase + wid * 16 + g;
    int r1 = r0 + 8;
    float d0 = (r0 < n) ? g_dis[r0] : 0.f;
    float d1 = (r1 < n) ? g_dis[r1] : 0.f;
    #pragma unroll
    for (int cb = 0; cb < 8; cb++) {
        int c = cb * 8 + cq;
        float bx = bs[c], by = bs[c + 1];
        if (r0 < n) {
            float v0 = fmaxf(acc[cb][0] + bx, 0.f);
            float v1 = fmaxf(acc[cb][1] + by, 0.f);
            *(float2*)(g_h0 + (size_t)r0 * HID + c) = make_float2(v0, v1);
            g_hsA[(size_t)r0 * 32 + (c >> 1)] = __floats2half2_rn(d0 * v0, d0 * v1);
        }
        if (r1 < n) {
            float v0 = fmaxf(acc[cb][2] + bx, 0.f);
            float v1 = fmaxf(acc[cb][3] + by, 0.f);
            *(float2*)(g_h0 + (size_t)r1 * HID + c) = make_float2(v0, v1);
            g_hsA[(size_t)r1 * 32 + (c >> 1)] = __floats2half2_rn(d1 * v0, d1 * v1);
        }
    }
}

// ---------------- Propagation hop (4-deep scalar, known-good) ----------------
// hs = dis (.) h (fp16).  out[v] = 0.9*dis[v]*(sum_{edges} hs[src] + hs[v]) + 0.1*h0[v]
__global__ __launch_bounds__(256) void k_hop(const __half2* __restrict__ hs,
                                             __half2* __restrict__ hn,
                                             int n, int final_hop) {
    int warp = (blockIdx.x * blockDim.x + threadIdx.x) >> 5;
    int lane = threadIdx.x & 31;
    if (warp >= n) return;
    int beg = g_colptr[warp], end = g_colptr[warp + 1];

    float2 self = __half22float2(hs[(size_t)warp * 32 + lane]);
    float ax0 = self.x, ay0 = self.y;
    float ax1 = 0.f, ay1 = 0.f;

    int e = beg;
    for (; e + 3 < end; e += 4) {
        int s0 = __ldg(&g_edge[e]);
        int s1 = __ldg(&g_edge[e + 1]);
        int s2 = __ldg(&g_edge[e + 2]);
        int s3 = __ldg(&g_edge[e + 3]);
        float2 f0 = __half22float2(hs[(size_t)s0 * 32 + lane]);
        float2 f1 = __half22float2(hs[(size_t)s1 * 32 + lane]);
        float2 f2 = __half22float2(hs[(size_t)s2 * 32 + lane]);
        float2 f3 = __half22float2(hs[(size_t)s3 * 32 + lane]);
        ax0 += f0.x; ay0 += f0.y;
        ax1 += f1.x; ay1 += f1.y;
        ax0 += f2.x; ay0 += f2.y;
        ax1 += f3.x; ay1 += f3.y;
    }
    for (; e < end; e++) {
        int s0 = __ldg(&g_edge[e]);
        float2 f0 = __half22float2(hs[(size_t)s0 * 32 + lane]);
        ax0 += f0.x; ay0 += f0.y;
    }
    float ax = ax0 + ax1, ay = ay0 + ay1;

    float d = g_dis[warp];
    float2 h0v = *(const float2*)(g_h0 + (size_t)warp * HID + lane * 2);
    float ox = 0.9f * d * ax + 0.1f * h0v.x;
    float oy = 0.9f * d * ay + 0.1f * h0v.y;

    if (final_hop) {
        *(float2*)(g_hF + (size_t)warp * HID + lane * 2) = make_float2(ox, oy);
    } else {
        hn[(size_t)warp * 32 + lane] = __floats2half2_rn(d * ox, d * oy);
    }
}

// ---------------- Predict + softmax family ----------------
__global__ __launch_bounds__(256) void k_pred(const float* __restrict__ h,
                                              const float* __restrict__ Wp,
                                              const float* __restrict__ bp,
                                              float* __restrict__ out,
                                              int n, int out_size) {
    __shared__ float Ws[HID * NCLS];
    __shared__ float bs[NCLS];
    __shared__ float hsm[8][HID];
    for (int i = threadIdx.x; i < HID * NCLS; i += blockDim.x) Ws[i] = Wp[i];
    if (threadIdx.x < NCLS) bs[threadIdx.x] = bp[threadIdx.x];
    __syncthreads();

    int warp = threadIdx.x >> 5;
    int lane = threadIdx.x & 31;
    int v = blockIdx.x * 8 + warp;
    if (v >= n) return;

    hsm[warp][lane]      = h[(size_t)v * HID + lane];
    hsm[warp][lane + 32] = h[(size_t)v * HID + lane + 32];
    __syncwarp();

    int c1 = (lane + 32 < NCLS) ? (lane + 32) : (NCLS - 1);
    float a0 = bs[lane];
    float a1 = bs[c1];
    #pragma unroll
    for (int k = 0; k < HID; k++) {
        float hk = hsm[warp][k];
        a0 += hk * Ws[k * NCLS + lane];
        a1 += hk * Ws[k * NCLS + c1];
    }
    bool l1 = (lane + 32 < NCLS);

    float m = fmaxf(a0, l1 ? a1 : -INFINITY);
    #pragma unroll
    for (int o = 16; o > 0; o >>= 1) m = fmaxf(m, __shfl_xor_sync(0xffffffff, m, o));
    float e0 = __expf(a0 - m);
    float e1 = l1 ? __expf(a1 - m) : 0.f;
    float s = e0 + e1;
    #pragma unroll
    for (int o = 16; o > 0; o >>= 1) s += __shfl_xor_sync(0xffffffff, s, o);
    float lse = m + logf(s);
    float inv = 1.f / s;

    size_t base = (size_t)v * NCLS;
    size_t sec  = (size_t)n * NCLS;
    out[base + lane] = a0 - lse;
    if (l1) out[base + lane + 32] = a1 - lse;
    if (out_size >= 2 * (int)sec) {
        out[sec + base + lane] = a0;
        if (l1) out[sec + base + lane + 32] = a1;
    }
    if (out_size >= 3 * (int)sec) {
        out[2 * sec + base + lane] = e0 * inv;
        if (l1) out[2 * sec + base + lane + 32] = e1 * inv;
    }
}

// ---------------- launch ----------------
extern "C" void kernel_launch(void* const* d_in, const int* in_sizes, int n_in,
                              void* d_out, int out_size) {
    const float* x     = (const float*)d_in[0];   // [N,512]
    const int*   eidx  = (const int*)d_in[1];     // [2,E]
    const float* Wemb  = (const float*)d_in[2];   // [512,64]
    const float* bemb  = (const float*)d_in[3];   // [64]
    const float* Wpred = (const float*)d_in[4];   // [64,47]
    const float* bpred = (const float*)d_in[5];   // [47]
    float* out = (float*)d_out;

    int n = in_sizes[0] / FIN;
    int e = in_sizes[1] / 2;
    const int* row = eidx;       // source
    const int* col = eidx + e;   // target

    int nbE  = (e + 255) / 256;
    int nbE4 = (e / 4 + 255) / 256 + 1;
    int nbS  = (n + 1023) / 1024;
    int total = n * FIN;

    cudaStream_t s2;
    cudaStreamCreate(&s2);
    cudaEvent_t evFork, evDis, evEmb;
    cudaEventCreateWithFlags(&evFork, cudaEventDisableTiming);
    cudaEventCreateWithFlags(&evDis,  cudaEventDisableTiming);
    cudaEventCreateWithFlags(&evEmb,  cudaEventDisableTiming);
    cudaStream_t s0 = (cudaStream_t)0;   // same default stream the <<<>>> launches use

    // fork: side stream converts W and X (depend only on inputs)
    cudaEventRecord(evFork, s0);
    cudaStreamWaitEvent(s2, evFork, 0);
    k_wconv<<<(FIN * HID + 255) / 256, 256, 0, s2>>>(Wemb);
    k_xconv<<<(total / 8 + 255) / 256, 256, 0, s2>>>(x, total);

    // main: degree histogram + scan (produces g_dis)
    {
        void* cntp; cudaGetSymbolAddress(&cntp, g_count);
        cudaMemsetAsync(cntp, 0, (size_t)n * sizeof(int), s0);
    }
    k_hist<<<nbE4, 256>>>(col, e);
    k_scan_block<<<nbS, 1024>>>(n);   // also computes g_dis
    cudaEventRecord(evDis, s0);

    // side: embed GEMM (needs g_dis for epilogue scaling + converted X/W)
    cudaStreamWaitEvent(s2, evDis, 0);
    k_embed_mma<<<(n + 127) / 128, 256, 0, s2>>>(bemb, n);
    cudaEventRecord(evEmb, s2);

    // main (overlapping with embed): finish CSR build
    k_scan_sums<<<1, 32>>>(nbS);
    k_finalize<<<nbS, 1024>>>(n);
    k_scatter_edges<<<nbE, 256>>>(row, col, e);

    // join: hops need both CSR (main) and h0/hsA (side)
    cudaStreamWaitEvent(s0, evEmb, 0);

    // --- 10 propagation hops (ping-pong fp16 scaled state) ---
    int hopBlocks = (n * 32 + 255) / 256;
    {
        __half2* hAp; cudaGetSymbolAddress((void**)&hAp, g_hsA);
        __half2* hBp; cudaGetSymbolAddress((void**)&hBp, g_hsB);
        __half2* cur = hAp;
        for (int i = 0; i < KHOPS; i++) {
            int fin = (i == KHOPS - 1);
            __half2* dst = (cur == hAp) ? hBp : hAp;
            k_hop<<<hopBlocks, 256>>>(cur, dst, n, fin);
            cur = dst;
        }
    }

    // --- predict + softmax family (reads fp32 g_hF) ---
    float* hFp; cudaGetSymbolAddress((void**)&hFp, g_hF);
    k_pred<<<(n + 7) / 8, 256>>>(hFp, Wpred, bpred, out, n, out_size);
}

// round 8
// speedup vs baseline: 1.2123x; 1.1323x over previous
#include <cuda_runtime.h>
#include <cuda_bf16.h>
#include <cuda_fp16.h>
#include <math.h>

// Problem constants (shapes are fixed for this problem instance)
#define NN      100000
#define NE      3200000
#define FIN     512
#define HID     64
#define NCLS    47
#define KHOPS   10
#define ALPHA   0.1f

// -------- device scratch (no allocations allowed) --------
__device__ int   g_count[NN];        // in-degree counts (real edges only)
__device__ int   g_colptr[NN + 1];   // CSR row pointers (by destination)
__device__ int   g_cursor[NN];       // scatter cursors
__device__ float g_dis[NN];          // D^-1/2 (deg incl. self loop)
__device__ int   g_incl[NN];         // inclusive per-block scan temp
__device__ int   g_blksum[256];      // block sums for scan
__device__ __align__(16) int g_edge[NE + 8];  // src index, sorted by dst (+pad for pair reads)
__device__ __half g_Wt[(size_t)HID * FIN];                     // W^T fp16 [64][512]
__device__ __align__(16) __half g_X16[(size_t)(NN + 128) * FIN]; // X in fp16 (+pad rows)
__device__ __align__(256) __half2 g_h0h[(size_t)NN * 32]; // fp16 anchor (unscaled h0)
__device__ __align__(256) float g_hF[(size_t)NN * HID];   // final fp32 h
__device__ __align__(256) __half2 g_hsA[(size_t)NN * 32]; // scaled fp16 state
__device__ __align__(256) __half2 g_hsB[(size_t)NN * 32];

// ---------------- cp.async helpers ----------------
__device__ __forceinline__ void cp16(void* smem, const void* gmem) {
    unsigned s = (unsigned)__cvta_generic_to_shared(smem);
    asm volatile("cp.async.ca.shared.global [%0], [%1], 16;\n" :: "r"(s), "l"(gmem));
}
__device__ __forceinline__ void cp_commit() {
    asm volatile("cp.async.commit_group;\n");
}
template <int N>
__device__ __forceinline__ void cp_wait() {
    asm volatile("cp.async.wait_group %0;\n" :: "n"(N));
}

// ---------------- CSR build ----------------
__global__ void k_hist(const int* __restrict__ col, int e) {
    int i4 = (blockIdx.x * blockDim.x + threadIdx.x) * 4;
    if (i4 + 4 <= e) {
        int4 c = *(const int4*)(col + i4);
        atomicAdd(&g_count[c.x], 1);
        atomicAdd(&g_count[c.y], 1);
        atomicAdd(&g_count[c.z], 1);
        atomicAdd(&g_count[c.w], 1);
    } else {
        for (int i = i4; i < e; i++) atomicAdd(&g_count[col[i]], 1);
    }
}

// Hillis-Steele block scan (1024/block); also computes g_dis
__global__ void k_scan_block(int n) {
    __shared__ int s[1024];
    int i = blockIdx.x * 1024 + threadIdx.x;
    int v = (i < n) ? g_count[i] : 0;
    if (i < n) g_dis[i] = rsqrtf((float)(v + 1));  // +1 self loop
    s[threadIdx.x] = v;
    __syncthreads();
    #pragma unroll
    for (int off = 1; off < 1024; off <<= 1) {
        int t = (threadIdx.x >= off) ? s[threadIdx.x - off] : 0;
        __syncthreads();
        s[threadIdx.x] += t;
        __syncthreads();
    }
    if (i < n) g_incl[i] = s[threadIdx.x];
    if (threadIdx.x == 1023) g_blksum[blockIdx.x] = s[1023];
}

__global__ void k_scan_sums(int nb) {
    if (blockIdx.x == 0 && threadIdx.x == 0) {
        int acc = 0;
        for (int b = 0; b < nb; b++) { int t = g_blksum[b]; g_blksum[b] = acc; acc += t; }
    }
}

__global__ void k_finalize(int n) {
    int i = blockIdx.x * blockDim.x + threadIdx.x;
    if (i == 0) g_colptr[0] = 0;
    if (i < n) {
        int e = g_incl[i] + g_blksum[i >> 10];
        g_colptr[i + 1] = e;
        g_cursor[i] = e - g_count[i];
    }
}

__global__ void k_scatter_edges(const int* __restrict__ row, const int* __restrict__ col, int e) {
    int i = blockIdx.x * blockDim.x + threadIdx.x;
    if (i >= e) return;
    int c = col[i];
    int pos = atomicAdd(&g_cursor[c], 1);
    g_edge[pos] = row[i];
}

// ---------------- W preconvert: g_Wt[n][k] = (half)W[k][n] ----------------
__global__ void k_wconv(const float* __restrict__ W) {
    int i = blockIdx.x * blockDim.x + threadIdx.x;
    if (i < FIN * HID) {
        int k = i >> 6, nn = i & 63;
        g_Wt[(size_t)nn * FIN + k] = __float2half(W[(size_t)k * HID + nn]);
    }
}

// ---------------- X preconvert: fp32 -> fp16 ----------------
__global__ __launch_bounds__(256) void k_xconv(const float* __restrict__ X, int total) {
    int i = (blockIdx.x * blockDim.x + threadIdx.x) * 8;
    if (i + 8 <= total) {
        float4 a = *(const float4*)(X + i);
        float4 b = *(const float4*)(X + i + 4);
        __half2 h0 = __floats2half2_rn(a.x, a.y);
        __half2 h1 = __floats2half2_rn(a.z, a.w);
        __half2 h2 = __floats2half2_rn(b.x, b.y);
        __half2 h3 = __floats2half2_rn(b.z, b.w);
        uint4 v;
        v.x = *(unsigned*)&h0; v.y = *(unsigned*)&h1;
        v.z = *(unsigned*)&h2; v.w = *(unsigned*)&h3;
        *(uint4*)(g_X16 + i) = v;
    } else {
        for (int j = i; j < total; j++) g_X16[j] = __float2half(X[j]);
    }
}

// ---------------- Embed GEMM via tensor cores, cp.async double-buffered ----------------
#define KC 32
#define XSTR (KC + 8)      // padded smem row stride in halves
#define NCHUNK (FIN / KC)  // 16
__global__ __launch_bounds__(256) void k_embed_mma(const float* __restrict__ b, int n) {
    __shared__ __align__(16) __half Xs[2][128][XSTR];
    __shared__ __align__(16) __half Ws[2][64][XSTR];
    __shared__ float bs[HID];
    int tid = threadIdx.x;
    int wid = tid >> 5, lane = tid & 31;
    int g  = lane >> 2;          // 0..7
    int cq = (lane & 3) * 2;     // 0,2,4,6
    int rowBase = blockIdx.x * 128;
    if (tid < HID) bs[tid] = b[tid];

    int xr = tid >> 1;
    int xp = (tid & 1) * 16;
    const __half* xsrc = g_X16 + (size_t)(rowBase + xr) * FIN + xp;
    int wr = tid >> 2;
    int wq = (tid & 3) * 8;
    const __half* wsrc = g_Wt + (size_t)wr * FIN + wq;

    float acc[8][4];
    #pragma unroll
    for (int i = 0; i < 8; i++)
        #pragma unroll
        for (int j = 0; j < 4; j++) acc[i][j] = 0.f;

    cp16(&Xs[0][xr][xp],     xsrc);
    cp16(&Xs[0][xr][xp + 8], xsrc + 8);
    cp16(&Ws[0][wr][wq],     wsrc);
    cp_commit();

    for (int c = 0; c < NCHUNK; c++) {
        int st = c & 1;
        if (c + 1 < NCHUNK) {
            int ns = (c + 1) & 1;
            int k0 = (c + 1) * KC;
            cp16(&Xs[ns][xr][xp],     xsrc + k0);
            cp16(&Xs[ns][xr][xp + 8], xsrc + k0 + 8);
            cp16(&Ws[ns][wr][wq],     wsrc + k0);
            cp_commit();
            cp_wait<1>();
        } else {
            cp_wait<0>();
        }
        __syncthreads();

        #pragma unroll
        for (int kk = 0; kk < KC; kk += 16) {
            unsigned a0 = *(const unsigned*)&Xs[st][wid * 16 + g][kk + cq];
            unsigned a1 = *(const unsigned*)&Xs[st][wid * 16 + g + 8][kk + cq];
            unsigned a2 = *(const unsigned*)&Xs[st][wid * 16 + g][kk + cq + 8];
            unsigned a3 = *(const unsigned*)&Xs[st][wid * 16 + g + 8][kk + cq + 8];
            #pragma unroll
            for (int cb = 0; cb < 8; cb++) {
                unsigned b0 = *(const unsigned*)&Ws[st][cb * 8 + g][kk + cq];
                unsigned b1 = *(const unsigned*)&Ws[st][cb * 8 + g][kk + cq + 8];
                asm volatile(
                    "mma.sync.aligned.m16n8k16.row.col.f32.f16.f16.f32 "
                    "{%0,%1,%2,%3}, {%4,%5,%6,%7}, {%8,%9}, {%0,%1,%2,%3};"
                    : "+f"(acc[cb][0]), "+f"(acc[cb][1]),
                      "+f"(acc[cb][2]), "+f"(acc[cb][3])
                    : "r"(a0), "r"(a1), "r"(a2), "r"(a3), "r"(b0), "r"(b1));
            }
        }
        __syncthreads();
    }

    // epilogue: bias + relu -> fp16 anchor g_h0h and dis-scaled fp16 state g_hsA
    int r0 = rowBase + wid * 16 + g;
    int r1 = r0 + 8;
    float d0 = (r0 < n) ? g_dis[r0] : 0.f;
    float d1 = (r1 < n) ? g_dis[r1] : 0.f;
    #pragma unroll
    for (int cb = 0; cb < 8; cb++) {
        int c = cb * 8 + cq;
        float bx = bs[c], by = bs[c + 1];
        if (r0 < n) {
            float v0 = fmaxf(acc[cb][0] + bx, 0.f);
            float v1 = fmaxf(acc[cb][1] + by, 0.f);
            g_h0h[(size_t)r0 * 32 + (c >> 1)] = __floats2half2_rn(v0, v1);
            g_hsA[(size_t)r0 * 32 + (c >> 1)] = __floats2half2_rn(d0 * v0, d0 * v1);
        }
        if (r1 < n) {
            float v0 = fmaxf(acc[cb][2] + bx, 0.f);
            float v1 = fmaxf(acc[cb][3] + by, 0.f);
            g_h0h[(size_t)r1 * 32 + (c >> 1)] = __floats2half2_rn(v0, v1);
            g_hsA[(size_t)r1 * 32 + (c >> 1)] = __floats2half2_rn(d1 * v0, d1 * v1);
        }
    }
}

// ---------------- Propagation hop: pair-split half-warp gathers ----------------
// hs = dis (.) h (fp16, row = 16 uint2).  out[v] = 0.9*d_v*(sum hs[src] + hs[v]) + 0.1*h0[v]
// Lanes 0-15 (half 0) process even pair slots, lanes 16-31 (half 1) odd slots;
// each lane owns 4 features (uint2 = 2x half2). Halves combine via shfl_xor(16).
__device__ __forceinline__ void acc4(float& a0, float& a1, float& a2, float& a3, uint2 v) {
    float2 fl = __half22float2(*(__half2*)&v.x);
    float2 fh = __half22float2(*(__half2*)&v.y);
    a0 += fl.x; a1 += fl.y; a2 += fh.x; a3 += fh.y;
}

__global__ __launch_bounds__(256) void k_hop(const uint2* __restrict__ hs,
                                             uint2* __restrict__ hn,
                                             int n, int final_hop) {
    int warp = (blockIdx.x * blockDim.x + threadIdx.x) >> 5;
    int lane = threadIdx.x & 31;
    if (warp >= n) return;
    int half = lane >> 4;      // 0 or 1
    int sub  = lane & 15;      // feature group: 4 features each
    int beg = g_colptr[warp], end = g_colptr[warp + 1];

    float a0, a1, a2, a3;          // accumulator set A
    float b0 = 0.f, b1 = 0.f, b2 = 0.f, b3 = 0.f;  // set B (ILP)
    if (half == 0) {               // self loop counted once
        uint2 s = hs[(size_t)warp * 16 + sub];
        float2 fl = __half22float2(*(__half2*)&s.x);
        float2 fh = __half22float2(*(__half2*)&s.y);
        a0 = fl.x; a1 = fl.y; a2 = fh.x; a3 = fh.y;
    } else {
        a0 = a1 = a2 = a3 = 0.f;
    }

    int e = beg;
    for (; e + 8 <= end; e += 8) {    // 4 pairs = 8 edges per iteration
        int i0 = __ldg(&g_edge[e     + half]);
        int i1 = __ldg(&g_edge[e + 2 + half]);
        int i2 = __ldg(&g_edge[e + 4 + half]);
        int i3 = __ldg(&g_edge[e + 6 + half]);
        uint2 v0 = hs[(size_t)i0 * 16 + sub];
        uint2 v1 = hs[(size_t)i1 * 16 + sub];
        uint2 v2 = hs[(size_t)i2 * 16 + sub];
        uint2 v3 = hs[(size_t)i3 * 16 + sub];
        acc4(a0, a1, a2, a3, v0);
        acc4(b0, b1, b2, b3, v1);
        acc4(a0, a1, a2, a3, v2);
        acc4(b0, b1, b2, b3, v3);
    }
    for (; e + 2 <= end; e += 2) {    // single pair
        int i0 = __ldg(&g_edge[e + half]);
        uint2 v0 = hs[(size_t)i0 * 16 + sub];
        acc4(a0, a1, a2, a3, v0);
    }
    if (e < end && half == 0) {       // odd tail edge: half 0 only
        int i0 = __ldg(&g_edge[e]);
        uint2 v0 = hs[(size_t)i0 * 16 + sub];
        acc4(a0, a1, a2, a3, v0);
    }
    a0 += b0; a1 += b1; a2 += b2; a3 += b3;
    a0 += __shfl_xor_sync(0xffffffffu, a0, 16);
    a1 += __shfl_xor_sync(0xffffffffu, a1, 16);
    a2 += __shfl_xor_sync(0xffffffffu, a2, 16);
    a3 += __shfl_xor_sync(0xffffffffu, a3, 16);

    float d = g_dis[warp];
    uint2 hz = *(const uint2*)(g_h0h + (size_t)warp * 32 + sub * 2);
    float2 zl = __half22float2(*(__half2*)&hz.x);
    float2 zh = __half22float2(*(__half2*)&hz.y);
    float o0 = 0.9f * d * a0 + 0.1f * zl.x;
    float o1 = 0.9f * d * a1 + 0.1f * zl.y;
    float o2 = 0.9f * d * a2 + 0.1f * zh.x;
    float o3 = 0.9f * d * a3 + 0.1f * zh.y;

    if (half == 0) {
        if (final_hop) {
            *(float4*)(g_hF + (size_t)warp * HID + sub * 4) = make_float4(o0, o1, o2, o3);
        } else {
            __half2 p0 = __floats2half2_rn(d * o0, d * o1);
            __half2 p1 = __floats2half2_rn(d * o2, d * o3);
            uint2 w;
            w.x = *(unsigned*)&p0;
            w.y = *(unsigned*)&p1;
            hn[(size_t)warp * 16 + sub] = w;
        }
    }
}

// ---------------- Predict + softmax family ----------------
__global__ __launch_bounds__(256) void k_pred(const float* __restrict__ h,
                                              const float* __restrict__ Wp,
                                              const float* __restrict__ bp,
                                              float* __restrict__ out,
                                              int n, int out_size) {
    __shared__ float Ws[HID * NCLS];
    __shared__ float bs[NCLS];
    __shared__ float hsm[8][HID];
    for (int i = threadIdx.x; i < HID * NCLS; i += blockDim.x) Ws[i] = Wp[i];
    if (threadIdx.x < NCLS) bs[threadIdx.x] = bp[threadIdx.x];
    __syncthreads();

    int warp = threadIdx.x >> 5;
    int lane = threadIdx.x & 31;
    int v = blockIdx.x * 8 + warp;
    if (v >= n) return;

    hsm[warp][lane]      = h[(size_t)v * HID + lane];
    hsm[warp][lane + 32] = h[(size_t)v * HID + lane + 32];
    __syncwarp();

    int c1 = (lane + 32 < NCLS) ? (lane + 32) : (NCLS - 1);
    float a0 = bs[lane];
    float a1 = bs[c1];
    #pragma unroll
    for (int k = 0; k < HID; k++) {
        float hk = hsm[warp][k];
        a0 += hk * Ws[k * NCLS + lane];
        a1 += hk * Ws[k * NCLS + c1];
    }
    bool l1 = (lane + 32 < NCLS);

    float m = fmaxf(a0, l1 ? a1 : -INFINITY);
    #pragma unroll
    for (int o = 16; o > 0; o >>= 1) m = fmaxf(m, __shfl_xor_sync(0xffffffff, m, o));
    float e0 = __expf(a0 - m);
    float e1 = l1 ? __expf(a1 - m) : 0.f;
    float s = e0 + e1;
    #pragma unroll
    for (int o = 16; o > 0; o >>= 1) s += __shfl_xor_sync(0xffffffff, s, o);
    float lse = m + logf(s);
    float inv = 1.f / s;

    size_t base = (size_t)v * NCLS;
    size_t sec  = (size_t)n * NCLS;
    out[base + lane] = a0 - lse;
    if (l1) out[base + lane + 32] = a1 - lse;
    if (out_size >= 2 * (int)sec) {
        out[sec + base + lane] = a0;
        if (l1) out[sec + base + lane + 32] = a1;
    }
    if (out_size >= 3 * (int)sec) {
        out[2 * sec + base + lane] = e0 * inv;
        if (l1) out[2 * sec + base + lane + 32] = e1 * inv;
    }
}

// ---------------- launch ----------------
extern "C" void kernel_launch(void* const* d_in, const int* in_sizes, int n_in,
                              void* d_out, int out_size) {
    const float* x     = (const float*)d_in[0];   // [N,512]
    const int*   eidx  = (const int*)d_in[1];     // [2,E]
    const float* Wemb  = (const float*)d_in[2];   // [512,64]
    const float* bemb  = (const float*)d_in[3];   // [64]
    const float* Wpred = (const float*)d_in[4];   // [64,47]
    const float* bpred = (const float*)d_in[5];   // [47]
    float* out = (float*)d_out;

    int n = in_sizes[0] / FIN;
    int e = in_sizes[1] / 2;
    const int* row = eidx;       // source
    const int* col = eidx + e;   // target

    int nbE  = (e + 255) / 256;
    int nbE4 = (e / 4 + 255) / 256 + 1;
    int nbS  = (n + 1023) / 1024;
    int total = n * FIN;

    cudaStream_t s2;
    cudaStreamCreate(&s2);
    cudaEvent_t evFork, evDis, evEmb;
    cudaEventCreateWithFlags(&evFork, cudaEventDisableTiming);
    cudaEventCreateWithFlags(&evDis,  cudaEventDisableTiming);
    cudaEventCreateWithFlags(&evEmb,  cudaEventDisableTiming);
    cudaStream_t s0 = (cudaStream_t)0;

    // fork: side stream converts W and X (depend only on inputs)
    cudaEventRecord(evFork, s0);
    cudaStreamWaitEvent(s2, evFork, 0);
    k_wconv<<<(FIN * HID + 255) / 256, 256, 0, s2>>>(Wemb);
    k_xconv<<<(total / 8 + 255) / 256, 256, 0, s2>>>(x, total);

    // main: degree histogram + scan (produces g_dis)
    {
        void* cntp; cudaGetSymbolAddress(&cntp, g_count);
        cudaMemsetAsync(cntp, 0, (size_t)n * sizeof(int), s0);
    }
    k_hist<<<nbE4, 256>>>(col, e);
    k_scan_block<<<nbS, 1024>>>(n);   // also computes g_dis
    cudaEventRecord(evDis, s0);

    // side: embed GEMM (needs g_dis + converted X/W)
    cudaStreamWaitEvent(s2, evDis, 0);
    k_embed_mma<<<(n + 127) / 128, 256, 0, s2>>>(bemb, n);
    cudaEventRecord(evEmb, s2);

    // main (overlapping with embed): finish CSR build
    k_scan_sums<<<1, 32>>>(nbS);
    k_finalize<<<nbS, 1024>>>(n);
    k_scatter_edges<<<nbE, 256>>>(row, col, e);

    // join
    cudaStreamWaitEvent(s0, evEmb, 0);

    // --- 10 propagation hops (ping-pong fp16 scaled state) ---
    int hopBlocks = (n * 32 + 255) / 256;
    {
        uint2* hAp; cudaGetSymbolAddress((void**)&hAp, g_hsA);
        uint2* hBp; cudaGetSymbolAddress((void**)&hBp, g_hsB);
        uint2* cur = hAp;
        for (int i = 0; i < KHOPS; i++) {
            int fin = (i == KHOPS - 1);
            uint2* dst = (cur == hAp) ? hBp : hAp;
            k_hop<<<hopBlocks, 256>>>(cur, dst, n, fin);
            cur = dst;
        }
    }

    // --- predict + softmax family (reads fp32 g_hF) ---
    float* hFp; cudaGetSymbolAddress((void**)&hFp, g_hF);
    k_pred<<<(n + 7) / 8, 256>>>(hFp, Wpred, bpred, out, n, out_size);
}